// round 2
// baseline (speedup 1.0000x reference)
#include <cuda_runtime.h>

// ---------------------------------------------------------------------------
// Quantized LeNet, exact fixed-point semantics.
// APREC=8, PPREC=8, IWIDTH=3 -> clamp to [-8.0, +7.0]  (QMAX = 2^3 - 1 = 7!)
// grid 1/256.
//
// Core trick: round_half_even(x * w256) == fmaf(x, w256, MAGIC) - MAGIC,
// with MAGIC = 1.5*2^23. We keep accumulators in int units of 1/256 and
// add __float_as_int(y) - 0x4B400000 (one IADD3 with immediate).
// ---------------------------------------------------------------------------

#define MAGICF 12582912.0f          // 1.5 * 2^23
#define MAGICI 0x4B400000           // bit pattern of MAGICF
#define CLAMP_LO (MAGICF - 2048.0f) // q = -2048  (-8.0)
#define CLAMP_HI (MAGICF + 1792.0f) // q = +1792  (+7.0)   <-- QMAX = 7.0

#define QLO (-2048)
#define QHI 1792

// Output layout (float offsets) — tuple order of reference():
#define OFF_LOGP   0
#define OFF_C1IN   20480      // [2048,1,28,28]
#define OFF_C1OUT  1626112    // [2048,10,24,24]
#define OFF_C2IN   13422592   // [2048,10,12,12]
#define OFF_C2OUT  16371712   // [2048,20,8,8]
#define OFF_FC1IN  18993152   // [2048,320]
#define OFF_FC1OUT 19648512   // [2048,50]
#define OFF_FC2IN  19750912   // [2048,50]
#define OFF_FC2OUT 19853312   // [2048,10]

// Prequantized parameters (device scratch — no allocations).
__device__ float g_w1[256];              // conv1 w * 256 (rounded), [10][25]
__device__ int   g_b1[16];               // conv1 b * 256 (rounded)
__device__ float g_w2p[20 * 10 * 5 * 8]; // conv2 w * 256, q padded to 8
__device__ int   g_b2[32];               // conv2 b * 256
__device__ int   g_f1w[16000];           // fc1 w: clamp(round(w*256), -2048, 1792)
__device__ int   g_f1b[64];
__device__ int   g_f2w[512];
__device__ int   g_f2b[16];

__device__ __forceinline__ int iclamp(int v, int lo, int hi) {
    return v < lo ? lo : (v > hi ? hi : v);
}

// round-half-even of S/256 for integer S
__device__ __forceinline__ int rhe8(int S) {
    return (S + 127 + ((S >> 8) & 1)) >> 8;
}

// ---------------------------------------------------------------------------
__global__ void prep_kernel(const float* __restrict__ w1, const float* __restrict__ b1,
                            const float* __restrict__ w2, const float* __restrict__ b2,
                            const float* __restrict__ f1w, const float* __restrict__ f1b,
                            const float* __restrict__ f2w, const float* __restrict__ f2b) {
    int t = blockIdx.x * blockDim.x + threadIdx.x;
    int stride = gridDim.x * blockDim.x;
    // conv weights/bias: quant only (no clamp in fixed_point_conv on w/b)
    for (int i = t; i < 250; i += stride) g_w1[i] = rintf(w1[i] * 256.0f);
    for (int i = t; i < 10; i += stride) g_b1[i] = __float2int_rn(b1[i] * 256.0f);
    // conv2 weights into padded layout [cout][cin][p][8]
    for (int i = t; i < 8000; i += stride) {
        int q = i & 7;
        int rest = i >> 3;            // (cout*10+cin)*5 + p
        int p = rest % 5;
        int cc = rest / 5;            // cout*10+cin
        int cin = cc % 10;
        int cout = cc / 10;
        float v = 0.0f;
        if (q < 5) v = rintf(w2[((cout * 10 + cin) * 5 + p) * 5 + q] * 256.0f);
        g_w2p[i] = v;
    }
    for (int i = t; i < 20; i += stride) g_b2[i] = __float2int_rn(b2[i] * 256.0f);
    // fc weights/bias: round_max(quant(.)) -> clamp to [-8, +7] = [-2048, 1792]
    for (int i = t; i < 16000; i += stride)
        g_f1w[i] = iclamp(__float2int_rn(f1w[i] * 256.0f), QLO, QHI);
    for (int i = t; i < 50; i += stride)
        g_f1b[i] = iclamp(__float2int_rn(f1b[i] * 256.0f), QLO, QHI);
    for (int i = t; i < 500; i += stride)
        g_f2w[i] = iclamp(__float2int_rn(f2w[i] * 256.0f), QLO, QHI);
    for (int i = t; i < 10; i += stride)
        g_f2b[i] = iclamp(__float2int_rn(f2b[i] * 256.0f), QLO, QHI);
}

// ---------------------------------------------------------------------------
// quantize input x -> conv1_input region (1,605,632 floats = 401,408 float4)
__global__ void quantx_kernel(const float4* __restrict__ x, float4* __restrict__ out) {
    int i = blockIdx.x * blockDim.x + threadIdx.x;
    if (i >= 401408) return;
    float4 v = x[i];
    v.x = rintf(v.x * 256.0f) * 0.00390625f;
    v.y = rintf(v.y * 256.0f) * 0.00390625f;
    v.z = rintf(v.z * 256.0f) * 0.00390625f;
    v.w = rintf(v.w * 256.0f) * 0.00390625f;
    out[i] = v;
}

// ---------------------------------------------------------------------------
// conv1: [2048,1,28,28] -> [2048,10,24,24]. Thread = (b, cout, row): 24 outputs.
__global__ void __launch_bounds__(128) conv1_kernel(float* __restrict__ dout) {
    int t = blockIdx.x * 128 + threadIdx.x; // 491,520 total, exact
    int b = t / 240;
    int r = t % 240;
    int co = r / 24;
    int row = r % 24;

    float wv[25];
#pragma unroll
    for (int i = 0; i < 25; i++) wv[i] = g_w1[co * 25 + i];
    int bq = g_b1[co];
    int acc[24];
#pragma unroll
    for (int j = 0; j < 24; j++) acc[j] = bq;

    const float* X = dout + OFF_C1IN + b * 784;
    for (int p = 0; p < 5; p++) {
        float xr[28];
        const float4* xp = (const float4*)(X + (row + p) * 28);
#pragma unroll
        for (int i = 0; i < 7; i++) {
            float4 v = xp[i];
            xr[4 * i + 0] = v.x; xr[4 * i + 1] = v.y;
            xr[4 * i + 2] = v.z; xr[4 * i + 3] = v.w;
        }
#pragma unroll
        for (int q = 0; q < 5; q++) {
            float w = wv[p * 5 + q];
#pragma unroll
            for (int j = 0; j < 24; j++) {
                float y = fmaf(xr[j + q], w, MAGICF);
                y = fminf(fmaxf(y, CLAMP_LO), CLAMP_HI);
                acc[j] += __float_as_int(y) - MAGICI;
            }
        }
    }

    float* O = dout + OFF_C1OUT + ((b * 10 + co) * 24 + row) * 24;
#pragma unroll
    for (int j = 0; j < 24; j += 4) {
        float4 v;
        v.x = __int2float_rn(acc[j + 0]) * 0.00390625f;
        v.y = __int2float_rn(acc[j + 1]) * 0.00390625f;
        v.z = __int2float_rn(acc[j + 2]) * 0.00390625f;
        v.w = __int2float_rn(acc[j + 3]) * 0.00390625f;
        *(float4*)(O + j) = v;
    }
}

// ---------------------------------------------------------------------------
// relu(maxpool2): generic. n outputs; W = output width; channel block = W*W.
__global__ void pool_kernel(const float* __restrict__ src, float* __restrict__ dst,
                            int n, int W) {
    int i = blockIdx.x * blockDim.x + threadIdx.x;
    if (i >= n) return;
    int c = i / (W * W);
    int rem = i % (W * W);
    int r = rem / W;
    int col = rem % W;
    int W2 = 2 * W;
    const float* s = src + c * (4 * W * W) + (2 * r) * W2 + 2 * col;
    float m = fmaxf(fmaxf(s[0], s[1]), fmaxf(s[W2], s[W2 + 1]));
    dst[i] = fmaxf(m, 0.0f);
}

// ---------------------------------------------------------------------------
// conv2: [2048,10,12,12] -> [2048,20,8,8]. Thread = (b, coutgroup of 4, row).
__global__ void __launch_bounds__(128) conv2_kernel(float* __restrict__ dout) {
    int t = blockIdx.x * 128 + threadIdx.x; // 81,920 total, exact
    int b = t / 40;
    int r = t % 40;
    int cg = r / 8;
    int row = r % 8;

    int acc[4][8];
#pragma unroll
    for (int u = 0; u < 4; u++) {
        int bq = g_b2[cg * 4 + u];
#pragma unroll
        for (int j = 0; j < 8; j++) acc[u][j] = bq;
    }

    const float* X = dout + OFF_C2IN + b * 1440;
    for (int ci = 0; ci < 10; ci++) {
        for (int p = 0; p < 5; p++) {
            float xr[12];
            const float4* xp = (const float4*)(X + ci * 144 + (row + p) * 12);
#pragma unroll
            for (int i = 0; i < 3; i++) {
                float4 v = xp[i];
                xr[4 * i + 0] = v.x; xr[4 * i + 1] = v.y;
                xr[4 * i + 2] = v.z; xr[4 * i + 3] = v.w;
            }
#pragma unroll
            for (int u = 0; u < 4; u++) {
                const float* wp = &g_w2p[(((cg * 4 + u) * 10 + ci) * 5 + p) * 8];
                float4 w03 = *(const float4*)wp;
                float wq[5] = {w03.x, w03.y, w03.z, w03.w, wp[4]};
#pragma unroll
                for (int q = 0; q < 5; q++) {
                    float w = wq[q];
#pragma unroll
                    for (int j = 0; j < 8; j++) {
                        float y = fmaf(xr[j + q], w, MAGICF);
                        y = fminf(fmaxf(y, CLAMP_LO), CLAMP_HI);
                        acc[u][j] += __float_as_int(y) - MAGICI;
                    }
                }
            }
        }
    }

#pragma unroll
    for (int u = 0; u < 4; u++) {
        float* O = dout + OFF_C2OUT + ((b * 20 + cg * 4 + u) * 8 + row) * 8;
#pragma unroll
        for (int j = 0; j < 8; j += 4) {
            float4 v;
            v.x = __int2float_rn(acc[u][j + 0]) * 0.00390625f;
            v.y = __int2float_rn(acc[u][j + 1]) * 0.00390625f;
            v.z = __int2float_rn(acc[u][j + 2]) * 0.00390625f;
            v.w = __int2float_rn(acc[u][j + 3]) * 0.00390625f;
            *(float4*)(O + j) = v;
        }
    }
}

// ---------------------------------------------------------------------------
// FC1 -> relu -> FC2 -> log_softmax. 2 batch rows per 128-thread block.
__global__ void __launch_bounds__(128) fc_kernel(float* __restrict__ dout) {
    __shared__ int   xq[2][320];
    __shared__ int   x2[2][64];
    __shared__ float v2[2][16];

    int sub = threadIdx.x >> 6;
    int lane = threadIdx.x & 63;
    int rowI = blockIdx.x * 2 + sub;

    const float* xin = dout + OFF_FC1IN + rowI * 320;
    for (int k = lane; k < 320; k += 64) {
        int q = __float2int_rn(xin[k] * 256.0f);
        xq[sub][k] = iclamp(q, QLO, QHI);   // round_max -> [-8, +7]
    }
    __syncthreads();

    if (lane < 50) {
        int S = g_f1b[lane] << 8;
        const int* w = &g_f1w[lane * 320];
#pragma unroll 8
        for (int k = 0; k < 320; k++) S += xq[sub][k] * w[k];
        S = iclamp(S, -524288, 458752); // [-8, 7] * 65536
        int q = rhe8(S);
        float f = q * 0.00390625f;
        dout[OFF_FC1OUT + rowI * 50 + lane] = f;
        int qr = q > 0 ? q : 0;
        dout[OFF_FC2IN + rowI * 50 + lane] = qr * 0.00390625f;
        x2[sub][lane] = qr;
    }
    __syncthreads();

    if (lane < 10) {
        int S = g_f2b[lane] << 8;
        const int* w = &g_f2w[lane * 50];
#pragma unroll
        for (int k = 0; k < 50; k++) S += x2[sub][k] * w[k];
        S = iclamp(S, -524288, 458752);
        int q = rhe8(S);
        float f = q * 0.00390625f;
        dout[OFF_FC2OUT + rowI * 10 + lane] = f;
        v2[sub][lane] = f;
    }
    __syncthreads();

    if (lane < 10) {
        float m = -1e30f;
#pragma unroll
        for (int k = 0; k < 10; k++) m = fmaxf(m, v2[sub][k]);
        float s = 0.0f;
#pragma unroll
        for (int k = 0; k < 10; k++) s += expf(v2[sub][k] - m);
        dout[OFF_LOGP + rowI * 10 + lane] = v2[sub][lane] - m - logf(s);
    }
}

// ---------------------------------------------------------------------------
extern "C" void kernel_launch(void* const* d_in, const int* in_sizes, int n_in,
                              void* d_out, int out_size) {
    const float* x   = (const float*)d_in[0];
    const float* w1  = (const float*)d_in[1];
    const float* b1  = (const float*)d_in[2];
    const float* w2  = (const float*)d_in[3];
    const float* b2  = (const float*)d_in[4];
    const float* f1w = (const float*)d_in[5];
    const float* f1b = (const float*)d_in[6];
    const float* f2w = (const float*)d_in[7];
    const float* f2b = (const float*)d_in[8];
    float* out = (float*)d_out;

    prep_kernel<<<32, 256>>>(w1, b1, w2, b2, f1w, f1b, f2w, f2b);
    quantx_kernel<<<(401408 + 255) / 256, 256>>>((const float4*)x,
                                                 (float4*)(out + OFF_C1IN));
    conv1_kernel<<<3840, 128>>>(out);
    pool_kernel<<<(2949120 + 255) / 256, 256>>>(out + OFF_C1OUT, out + OFF_C2IN,
                                                2949120, 12);
    conv2_kernel<<<640, 128>>>(out);
    pool_kernel<<<(655360 + 255) / 256, 256>>>(out + OFF_C2OUT, out + OFF_FC1IN,
                                               655360, 4);
    fc_kernel<<<1024, 128>>>(out);
}

// round 3
// speedup vs baseline: 1.3817x; 1.3817x over previous
#include <cuda_runtime.h>

// ---------------------------------------------------------------------------
// Quantized LeNet, exact fixed-point semantics.
// APREC=8, PPREC=8, IWIDTH=3 -> clamp to [-8.0, +7.0], grid 1/256.
//
// round_half_even(x * w256) == fmaf(x, w256, MAGIC) - MAGIC (MAGIC=1.5*2^23).
// Accumulate in int counts: acc += __float_as_int(y) - 0x4B400000 (one IADD3).
//
// Fast path: if max|x_cnt| * max|w_cnt| <= 458624 no product can leave
// [-2048, 1792] counts, so the clamp is the identity -> 2 instr/product.
// A clamped fallback kernel is always launched and self-selects via the
// inverted flag (uniform early exit), so the result is exact for ANY input.
// ---------------------------------------------------------------------------

#define MAGICF 12582912.0f          // 1.5 * 2^23
#define MAGICI 0x4B400000
#define CLAMP_LO (MAGICF - 2048.0f) // -8.0
#define CLAMP_HI (MAGICF + 1792.0f) // +7.0
#define QLO (-2048)
#define QHI 1792
#define SAFE_BOUND 458624           // (1792*256 - 128), conservative

// Output layout (float offsets) — tuple order of reference():
#define OFF_LOGP   0
#define OFF_C1IN   20480      // [2048,1,28,28]
#define OFF_C1OUT  1626112    // [2048,10,24,24]
#define OFF_C2IN   13422592   // [2048,10,12,12]
#define OFF_C2OUT  16371712   // [2048,20,8,8]
#define OFF_FC1IN  18993152   // [2048,320]
#define OFF_FC1OUT 19648512   // [2048,50]
#define OFF_FC2IN  19750912   // [2048,50]
#define OFF_FC2OUT 19853312   // [2048,10]

// Prequantized parameters + flags (device scratch — no allocations).
__device__ float g_w1[256];              // conv1 w*256, [10][25]
__device__ int   g_b1[16];
__device__ float g_w2p[8000];            // conv2 w*256, [20][10][5][8] (q pad 8)
__device__ int   g_b2[32];
__device__ int   g_f1w[16000];
__device__ int   g_f1b[64];
__device__ int   g_f2w[512];
__device__ int   g_f2b[16];
__device__ int   g_maxx;                 // max |x| counts (conv1 input)
__device__ int   g_maxc1;                // max conv1-out counts (>=0, bounds conv2 in)
__device__ int   g_maxw1;                // max |w1| counts
__device__ int   g_maxw2;                // max |w2| counts

__device__ __forceinline__ int iclamp(int v, int lo, int hi) {
    return v < lo ? lo : (v > hi ? hi : v);
}
__device__ __forceinline__ int rhe8(int S) {       // round-half-even of S/256
    return (S + 127 + ((S >> 8) & 1)) >> 8;
}

template <int NW>
__device__ __forceinline__ void blockAtomicMax(int v, int* dst) {
    __shared__ int sm[NW];
    v = __reduce_max_sync(0xffffffffu, v);
    int w = threadIdx.x >> 5;
    if ((threadIdx.x & 31) == 0) sm[w] = v;
    __syncthreads();
    if (threadIdx.x == 0) {
        int m = sm[0];
#pragma unroll
        for (int i = 1; i < NW; i++) m = max(m, sm[i]);
        atomicMax(dst, m);
    }
}

__device__ __forceinline__ void loadrow28(float* xr, const float* p) {
#pragma unroll
    for (int i = 0; i < 7; i++) {
        float4 v = ((const float4*)p)[i];
        xr[4 * i + 0] = v.x; xr[4 * i + 1] = v.y;
        xr[4 * i + 2] = v.z; xr[4 * i + 3] = v.w;
    }
}

// ---------------------------------------------------------------------------
__global__ void prep_kernel(const float* __restrict__ w1, const float* __restrict__ b1,
                            const float* __restrict__ w2, const float* __restrict__ b2,
                            const float* __restrict__ f1w, const float* __restrict__ f1b,
                            const float* __restrict__ f2w, const float* __restrict__ f2b) {
    __shared__ int sm1[8], sm2[8];
    int t = threadIdx.x;
    int m1 = 0, m2 = 0;
    for (int i = t; i < 250; i += 256) {
        float q = rintf(w1[i] * 256.0f);
        g_w1[i] = q;
        m1 = max(m1, abs((int)q));
    }
    for (int i = t; i < 10; i += 256) g_b1[i] = __float2int_rn(b1[i] * 256.0f);
    for (int i = t; i < 8000; i += 256) {
        int q = i & 7;
        int rest = i >> 3;
        int p = rest % 5;
        int cc = rest / 5;
        int cin = cc % 10;
        int cout = cc / 10;
        float v = 0.0f;
        if (q < 5) {
            v = rintf(w2[((cout * 10 + cin) * 5 + p) * 5 + q] * 256.0f);
            m2 = max(m2, abs((int)v));
        }
        g_w2p[i] = v;
    }
    for (int i = t; i < 20; i += 256) g_b2[i] = __float2int_rn(b2[i] * 256.0f);
    for (int i = t; i < 16000; i += 256)
        g_f1w[i] = iclamp(__float2int_rn(f1w[i] * 256.0f), QLO, QHI);
    for (int i = t; i < 50; i += 256)
        g_f1b[i] = iclamp(__float2int_rn(f1b[i] * 256.0f), QLO, QHI);
    for (int i = t; i < 500; i += 256)
        g_f2w[i] = iclamp(__float2int_rn(f2w[i] * 256.0f), QLO, QHI);
    for (int i = t; i < 10; i += 256)
        g_f2b[i] = iclamp(__float2int_rn(f2b[i] * 256.0f), QLO, QHI);

    m1 = __reduce_max_sync(0xffffffffu, m1);
    m2 = __reduce_max_sync(0xffffffffu, m2);
    if ((t & 31) == 0) { sm1[t >> 5] = m1; sm2[t >> 5] = m2; }
    __syncthreads();
    if (t == 0) {
        int a = sm1[0], b = sm2[0];
#pragma unroll
        for (int i = 1; i < 8; i++) { a = max(a, sm1[i]); b = max(b, sm2[i]); }
        g_maxw1 = a;
        g_maxw2 = b;
        g_maxx = 0;
        g_maxc1 = 0;
    }
}

// ---------------------------------------------------------------------------
// quantize input x -> conv1_input (401,408 float4s), track max |counts|.
__global__ void __launch_bounds__(256) quantx_kernel(const float4* __restrict__ x,
                                                     float4* __restrict__ out) {
    int i = blockIdx.x * 256 + threadIdx.x;   // grid exact: 1568*256
    float4 v = x[i];
    int q0 = __float2int_rn(v.x * 256.0f);
    int q1 = __float2int_rn(v.y * 256.0f);
    int q2 = __float2int_rn(v.z * 256.0f);
    int q3 = __float2int_rn(v.w * 256.0f);
    v.x = q0 * 0.00390625f; v.y = q1 * 0.00390625f;
    v.z = q2 * 0.00390625f; v.w = q3 * 0.00390625f;
    out[i] = v;
    int m = max(max(abs(q0), abs(q1)), max(abs(q2), abs(q3)));
    blockAtomicMax<8>(m, &g_maxx);
}

// ---------------------------------------------------------------------------
// conv1 fused with pool1: thread = (b, cout, R) computes output rows 2R,2R+1
// and the pooled+relu row R of conv2_input. 245,760 threads = 1920*128.
template <bool CLAMP>
__device__ __forceinline__ void conv1_body(float* __restrict__ dout) {
    int t = blockIdx.x * 128 + threadIdx.x;
    int b = t / 120;
    int r = t % 120;
    int co = r / 12;
    int R = r % 12;

    int bq = g_b1[co];
    int acc0[24], acc1[24];
#pragma unroll
    for (int j = 0; j < 24; j++) { acc0[j] = bq; acc1[j] = bq; }

    const float* X = dout + OFF_C1IN + b * 784 + R * 56;  // row 2R
    float xa[28], xb[28];
    loadrow28(xa, X);
    loadrow28(xb, X + 28);

#pragma unroll
    for (int p = 0; p < 5; p++) {
        float wq[5];
#pragma unroll
        for (int i = 0; i < 5; i++) wq[i] = g_w1[co * 25 + p * 5 + i];
#pragma unroll
        for (int q = 0; q < 5; q++) {
            float w = wq[q];
#pragma unroll
            for (int j = 0; j < 24; j++) {
                float y0 = fmaf(xa[j + q], w, MAGICF);
                float y1 = fmaf(xb[j + q], w, MAGICF);
                if (CLAMP) {
                    y0 = fminf(fmaxf(y0, CLAMP_LO), CLAMP_HI);
                    y1 = fminf(fmaxf(y1, CLAMP_LO), CLAMP_HI);
                }
                acc0[j] += __float_as_int(y0) - MAGICI;
                acc1[j] += __float_as_int(y1) - MAGICI;
            }
        }
        if (p < 4) {
#pragma unroll
            for (int j = 0; j < 28; j++) xa[j] = xb[j];
            loadrow28(xb, X + (p + 2) * 28);
        }
    }

    // write two conv1_output rows
    float* O = dout + OFF_C1OUT + ((b * 10 + co) * 24 + 2 * R) * 24;
#pragma unroll
    for (int j = 0; j < 24; j += 4) {
        float4 v0, v1;
        v0.x = __int2float_rn(acc0[j + 0]) * 0.00390625f;
        v0.y = __int2float_rn(acc0[j + 1]) * 0.00390625f;
        v0.z = __int2float_rn(acc0[j + 2]) * 0.00390625f;
        v0.w = __int2float_rn(acc0[j + 3]) * 0.00390625f;
        v1.x = __int2float_rn(acc1[j + 0]) * 0.00390625f;
        v1.y = __int2float_rn(acc1[j + 1]) * 0.00390625f;
        v1.z = __int2float_rn(acc1[j + 2]) * 0.00390625f;
        v1.w = __int2float_rn(acc1[j + 3]) * 0.00390625f;
        *(float4*)(O + j) = v0;
        *(float4*)(O + 24 + j) = v1;
    }

    // pooled + relu row -> conv2_input; track max for conv2's clamp bound
    int pc[12];
    int pmax = 0;
#pragma unroll
    for (int j = 0; j < 12; j++) {
        int m = max(max(acc0[2 * j], acc0[2 * j + 1]),
                    max(acc1[2 * j], acc1[2 * j + 1]));
        m = max(m, 0);
        pc[j] = m;
        pmax = max(pmax, m);
    }
    float* P = dout + OFF_C2IN + ((b * 10 + co) * 12 + R) * 12;
#pragma unroll
    for (int j = 0; j < 12; j += 4) {
        float4 v;
        v.x = pc[j + 0] * 0.00390625f;
        v.y = pc[j + 1] * 0.00390625f;
        v.z = pc[j + 2] * 0.00390625f;
        v.w = pc[j + 3] * 0.00390625f;
        *(float4*)(P + j) = v;
    }
    blockAtomicMax<4>(pmax, &g_maxc1);
}

__global__ void __launch_bounds__(128) conv1_fast(float* __restrict__ dout) {
    if ((long long)g_maxx * g_maxw1 > SAFE_BOUND) return;
    conv1_body<false>(dout);
}
__global__ void __launch_bounds__(128) conv1_slow(float* __restrict__ dout) {
    if ((long long)g_maxx * g_maxw1 <= SAFE_BOUND) return;
    conv1_body<true>(dout);
}

// ---------------------------------------------------------------------------
// conv2: [2048,10,12,12] -> [2048,20,8,8]. Thread = (b, coutgroup4, row).
template <bool CLAMP>
__device__ __forceinline__ void conv2_body(float* __restrict__ dout) {
    int t = blockIdx.x * 128 + threadIdx.x; // 81,920
    int b = t / 40;
    int r = t % 40;
    int cg = r / 8;
    int row = r % 8;

    int acc[4][8];
#pragma unroll
    for (int u = 0; u < 4; u++) {
        int bq = g_b2[cg * 4 + u];
#pragma unroll
        for (int j = 0; j < 8; j++) acc[u][j] = bq;
    }

    const float* X = dout + OFF_C2IN + b * 1440;
    for (int ci = 0; ci < 10; ci++) {
        for (int p = 0; p < 5; p++) {
            float xr[12];
            const float4* xp = (const float4*)(X + ci * 144 + (row + p) * 12);
#pragma unroll
            for (int i = 0; i < 3; i++) {
                float4 v = xp[i];
                xr[4 * i + 0] = v.x; xr[4 * i + 1] = v.y;
                xr[4 * i + 2] = v.z; xr[4 * i + 3] = v.w;
            }
#pragma unroll
            for (int u = 0; u < 4; u++) {
                const float* wp = &g_w2p[(((cg * 4 + u) * 10 + ci) * 5 + p) * 8];
                float4 w03 = *(const float4*)wp;
                float wq[5] = {w03.x, w03.y, w03.z, w03.w, wp[4]};
#pragma unroll
                for (int q = 0; q < 5; q++) {
                    float w = wq[q];
#pragma unroll
                    for (int j = 0; j < 8; j++) {
                        float y = fmaf(xr[j + q], w, MAGICF);
                        if (CLAMP) y = fminf(fmaxf(y, CLAMP_LO), CLAMP_HI);
                        acc[u][j] += __float_as_int(y) - MAGICI;
                    }
                }
            }
        }
    }

#pragma unroll
    for (int u = 0; u < 4; u++) {
        float* O = dout + OFF_C2OUT + ((b * 20 + cg * 4 + u) * 8 + row) * 8;
#pragma unroll
        for (int j = 0; j < 8; j += 4) {
            float4 v;
            v.x = __int2float_rn(acc[u][j + 0]) * 0.00390625f;
            v.y = __int2float_rn(acc[u][j + 1]) * 0.00390625f;
            v.z = __int2float_rn(acc[u][j + 2]) * 0.00390625f;
            v.w = __int2float_rn(acc[u][j + 3]) * 0.00390625f;
            *(float4*)(O + j) = v;
        }
    }
}

__global__ void __launch_bounds__(128) conv2_fast(float* __restrict__ dout) {
    if ((long long)g_maxc1 * g_maxw2 > SAFE_BOUND) return;
    conv2_body<false>(dout);
}
__global__ void __launch_bounds__(128) conv2_slow(float* __restrict__ dout) {
    if ((long long)g_maxc1 * g_maxw2 <= SAFE_BOUND) return;
    conv2_body<true>(dout);
}

// ---------------------------------------------------------------------------
// relu(maxpool2) for pool2 (W=4): float2 loads.
__global__ void __launch_bounds__(256) pool_kernel(const float* __restrict__ src,
                                                   float* __restrict__ dst,
                                                   int n, int W) {
    int i = blockIdx.x * 256 + threadIdx.x;
    if (i >= n) return;
    int c = i / (W * W);
    int rem = i % (W * W);
    int r = rem / W;
    int col = rem % W;
    int W2 = 2 * W;
    const float* base = src + c * (4 * W * W) + (2 * r) * W2 + 2 * col;
    float2 a = *(const float2*)base;
    float2 d = *(const float2*)(base + W2);
    float m = fmaxf(fmaxf(a.x, a.y), fmaxf(d.x, d.y));
    dst[i] = fmaxf(m, 0.0f);
}

// ---------------------------------------------------------------------------
// FC1 -> relu -> FC2 -> log_softmax. 2 batch rows per 128-thread block.
__global__ void __launch_bounds__(128) fc_kernel(float* __restrict__ dout) {
    __shared__ int   xq[2][320];
    __shared__ int   x2[2][64];
    __shared__ float v2[2][16];

    int sub = threadIdx.x >> 6;
    int lane = threadIdx.x & 63;
    int rowI = blockIdx.x * 2 + sub;

    const float* xin = dout + OFF_FC1IN + rowI * 320;
    for (int k = lane; k < 320; k += 64) {
        int q = __float2int_rn(xin[k] * 256.0f);
        xq[sub][k] = iclamp(q, QLO, QHI);
    }
    __syncthreads();

    if (lane < 50) {
        int S = g_f1b[lane] << 8;
        const int* w = &g_f1w[lane * 320];
#pragma unroll 8
        for (int k = 0; k < 320; k++) S += xq[sub][k] * w[k];
        S = iclamp(S, -524288, 458752); // [-8, 7] * 65536
        int q = rhe8(S);
        float f = q * 0.00390625f;
        dout[OFF_FC1OUT + rowI * 50 + lane] = f;
        int qr = q > 0 ? q : 0;
        dout[OFF_FC2IN + rowI * 50 + lane] = qr * 0.00390625f;
        x2[sub][lane] = qr;
    }
    __syncthreads();

    if (lane < 10) {
        int S = g_f2b[lane] << 8;
        const int* w = &g_f2w[lane * 50];
#pragma unroll
        for (int k = 0; k < 50; k++) S += x2[sub][k] * w[k];
        S = iclamp(S, -524288, 458752);
        int q = rhe8(S);
        float f = q * 0.00390625f;
        dout[OFF_FC2OUT + rowI * 10 + lane] = f;
        v2[sub][lane] = f;
    }
    __syncthreads();

    if (lane < 10) {
        float m = -1e30f;
#pragma unroll
        for (int k = 0; k < 10; k++) m = fmaxf(m, v2[sub][k]);
        float s = 0.0f;
#pragma unroll
        for (int k = 0; k < 10; k++) s += expf(v2[sub][k] - m);
        dout[OFF_LOGP + rowI * 10 + lane] = v2[sub][lane] - m - logf(s);
    }
}

// ---------------------------------------------------------------------------
extern "C" void kernel_launch(void* const* d_in, const int* in_sizes, int n_in,
                              void* d_out, int out_size) {
    const float* x   = (const float*)d_in[0];
    const float* w1  = (const float*)d_in[1];
    const float* b1  = (const float*)d_in[2];
    const float* w2  = (const float*)d_in[3];
    const float* b2  = (const float*)d_in[4];
    const float* f1w = (const float*)d_in[5];
    const float* f1b = (const float*)d_in[6];
    const float* f2w = (const float*)d_in[7];
    const float* f2b = (const float*)d_in[8];
    float* out = (float*)d_out;

    prep_kernel<<<1, 256>>>(w1, b1, w2, b2, f1w, f1b, f2w, f2b);
    quantx_kernel<<<1568, 256>>>((const float4*)x, (float4*)(out + OFF_C1IN));
    conv1_fast<<<1920, 128>>>(out);
    conv1_slow<<<1920, 128>>>(out);
    conv2_fast<<<640, 128>>>(out);
    conv2_slow<<<640, 128>>>(out);
    pool_kernel<<<2560, 256>>>(out + OFF_C2OUT, out + OFF_FC1IN, 655360, 4);
    fc_kernel<<<1024, 128>>>(out);
}